// round 7
// baseline (speedup 1.0000x reference)
#include <cuda_runtime.h>
#include <math.h>
#include <cstdint>
#include <cstddef>

#define NN    50000
#define NE    800000
#define NG    256
#define D_IN  128
#define D_HID 64
#define D_OUT 128

typedef unsigned long long ull;

// ---------------- device scratch (no allocations allowed) ----------------
__device__ int   g_deg[NN];
__device__ int   g_fill[NN];
__device__ int   g_rowptr[NN + 1];
__device__ float g_dinv[NN];
__device__ int   g_src[NE];
__device__ int   g_dst[NE];
__device__ __align__(16) int2 g_edge[NE];   // (src, norm-as-int) packed
__device__ __align__(16) float g_bufA[(size_t)NN * D_HID];
__device__ __align__(16) float g_bufB[(size_t)NN * D_HID];
__device__ float g_psum[NG * D_HID];
__device__ int   g_pcnt[NG];
__device__ int   g_idx64;   // 1 if edge_index/batch are int64, 0 if int32

// ---------------- f32x2 packed-math helpers ----------------
__device__ __forceinline__ void ffma2(ull& d, ull a, ull b) {
  asm("fma.rn.f32x2 %0, %1, %2, %0;" : "+l"(d) : "l"(a), "l"(b));
}
__device__ __forceinline__ ull fmul2(ull a, ull b) {
  ull d; asm("mul.rn.f32x2 %0, %1, %2;" : "=l"(d) : "l"(a), "l"(b)); return d;
}
__device__ __forceinline__ ull pack2(float lo, float hi) {
  ull d; asm("mov.b64 %0, {%1, %2};" : "=l"(d) : "f"(lo), "f"(hi)); return d;
}
__device__ __forceinline__ float2 unpack2(ull v) {
  float2 r; asm("mov.b64 {%0, %1}, %2;" : "=f"(r.x), "=f"(r.y) : "l"(v)); return r;
}

// gelu(tanh approx) == x * sigmoid(1.5957691*(x + 0.044715 x^3))
__device__ __forceinline__ float gelu_fast(float x) {
  float s = x + 0.044715f * x * x * x;
  return __fdividef(x, 1.0f + __expf(-1.59576912f * s));
}

__device__ __forceinline__ int load_idx(const void* p, long long i) {
  if (g_idx64) return (int)((const long long*)p)[i];
  return ((const int*)p)[i];
}

// ---------------- init + dtype detect (fused) ----------------
__global__ void init_kernel(const void* __restrict__ ei, int n_nodes, int N) {
  int i = blockIdx.x * blockDim.x + threadIdx.x;
  if (i == 0) {
    const long long* p = (const long long*)ei;
    int ok = 1;
    for (int k = 0; k < 64; k++) {
      long long v = p[k];
      if (v < 0 || v >= (long long)N) { ok = 0; break; }
    }
    g_idx64 = ok;
  }
  if (i < n_nodes) { g_deg[i] = 0; g_fill[i] = 0; }
  if (i < NG * D_HID) g_psum[i] = 0.0f;
  if (i < NG) g_pcnt[i] = 0;
}

__global__ void hist_kernel(const void* __restrict__ ei, int E) {
  int e = blockIdx.x * blockDim.x + threadIdx.x;
  if (e >= E) return;
  int s = load_idx(ei, e);
  int d = load_idx(ei, (long long)E + e);
  g_src[e] = s;
  g_dst[e] = d;
  atomicAdd(&g_deg[d], 1);
}

// single-block exclusive scan of g_deg -> g_rowptr, fused dinv
__global__ void scan_kernel(int n) {
  __shared__ int sums[1024];
  int tid   = threadIdx.x;
  int chunk = (n + 1023) >> 10;
  int start = tid * chunk;
  int end   = min(start + chunk, n);
  int s = 0;
  for (int i = start; i < end; i++) s += g_deg[i];
  sums[tid] = s;
  __syncthreads();
  for (int off = 1; off < 1024; off <<= 1) {
    int v = 0;
    if (tid >= off) v = sums[tid - off];
    __syncthreads();
    sums[tid] += v;
    __syncthreads();
  }
  int run = (tid == 0) ? 0 : sums[tid - 1];
  for (int i = start; i < end; i++) {
    int d = g_deg[i];
    g_rowptr[i] = run;
    g_dinv[i]   = rsqrtf((float)d + 1.0f);   // self-loop: deg+1
    run += d;
  }
  if (end == n) g_rowptr[n] = run;
}

__global__ void scatter_kernel(int E) {
  int e = blockIdx.x * blockDim.x + threadIdx.x;
  if (e >= E) return;
  int s = g_src[e];
  int d = g_dst[e];
  int pos = g_rowptr[d] + atomicAdd(&g_fill[d], 1);
  g_edge[pos] = make_int2(s, __float_as_int(g_dinv[s] * g_dinv[d]));
}

// ---------------- dense GEMM: H[M,64] = X[M,K] @ W[K,64], f32x2 ------------
// BM=128, KB=32, 256 threads. Per-thread 8 rows (4 packed pairs) x 4 cols.
// X transposed in smem (row pairs adjacent -> b64 loads); W duplicated in
// smem (float2 load == (w,w) operand). Inner loop = pure FFMA2 + LDS.b64.
template <int K>
__global__ void gemm_kernel(const float* __restrict__ X,
                            const float* __restrict__ W,
                            float* __restrict__ H, int M) {
  constexpr int NOUT = D_HID;
  constexpr int BM = 128;
  constexpr int KB = 32;
  constexpr int XS = BM + 4;                    // 132: rows stay 16B-aligned
  __shared__ __align__(16) float Xs[KB][XS];    // transposed: Xs[k][r]
  __shared__ __align__(16) float Wd[KB][2 * NOUT];

  int tid = threadIdx.x;
  int tx  = tid & 15;
  int ty  = tid >> 4;
  int rb  = blockIdx.x * BM;

  ull acc[4][4];
#pragma unroll
  for (int p = 0; p < 4; p++)
#pragma unroll
    for (int j = 0; j < 4; j++) acc[p][j] = 0ull;

  for (int k0 = 0; k0 < K; k0 += KB) {
#pragma unroll
    for (int i = tid; i < BM * KB; i += 256) {
      int r = i >> 5, k = i & 31;
      int gr = rb + r;
      Xs[k][r] = (gr < M) ? X[(size_t)gr * K + k0 + k] : 0.0f;
    }
#pragma unroll
    for (int i = tid; i < KB * NOUT; i += 256) {
      int k = i >> 6, c = i & 63;
      float v = W[(size_t)(k0 + k) * NOUT + c];
      Wd[k][2 * c]     = v;
      Wd[k][2 * c + 1] = v;
    }
    __syncthreads();
#pragma unroll
    for (int k = 0; k < KB; k++) {
      const ull* xp = reinterpret_cast<const ull*>(&Xs[k][ty * 8]);
      const ull* wp = reinterpret_cast<const ull*>(&Wd[k][tx * 8]);
      ull xr[4] = {xp[0], xp[1], xp[2], xp[3]};
      ull wr[4] = {wp[0], wp[1], wp[2], wp[3]};
#pragma unroll
      for (int p = 0; p < 4; p++)
#pragma unroll
        for (int j = 0; j < 4; j++) ffma2(acc[p][j], xr[p], wr[j]);
    }
    __syncthreads();
  }

#pragma unroll
  for (int p = 0; p < 4; p++) {
    int r0 = rb + ty * 8 + 2 * p;
    float2 c0 = unpack2(acc[p][0]);
    float2 c1 = unpack2(acc[p][1]);
    float2 c2 = unpack2(acc[p][2]);
    float2 c3 = unpack2(acc[p][3]);
    if (r0 < M)
      *reinterpret_cast<float4*>(H + (size_t)r0 * NOUT + tx * 4) =
          make_float4(c0.x, c1.x, c2.x, c3.x);
    if (r0 + 1 < M)
      *reinterpret_cast<float4*>(H + (size_t)(r0 + 1) * NOUT + tx * 4) =
          make_float4(c0.y, c1.y, c2.y, c3.y);
  }
}

// ------- CSR aggregation core (F=64, warp per node, f32x2) ------------------
__device__ __forceinline__ ull agg_node(const float* __restrict__ H,
                                        int n, int lane) {
  float dn = g_dinv[n];
  ull acc = __ldg(reinterpret_cast<const ull*>(H + (size_t)n * D_HID) + lane);
  acc = fmul2(acc, pack2(dn * dn, dn * dn));

  int e  = g_rowptr[n];
  int e1 = g_rowptr[n + 1];
  for (; e + 1 < e1; e += 2) {
    int2 v0 = __ldg(&g_edge[e]);
    int2 v1 = __ldg(&g_edge[e + 1]);
    ull h0 = __ldg(reinterpret_cast<const ull*>(H + (size_t)v0.x * D_HID) + lane);
    ull h1 = __ldg(reinterpret_cast<const ull*>(H + (size_t)v1.x * D_HID) + lane);
    float w0 = __int_as_float(v0.y);
    float w1 = __int_as_float(v1.y);
    ffma2(acc, h0, pack2(w0, w0));
    ffma2(acc, h1, pack2(w1, w1));
  }
  if (e < e1) {
    int2 v = __ldg(&g_edge[e]);
    ull h = __ldg(reinterpret_cast<const ull*>(H + (size_t)v.x * D_HID) + lane);
    float w = __int_as_float(v.y);
    ffma2(acc, h, pack2(w, w));
  }
  return acc;
}

__global__ void agg_gelu_kernel(const float* __restrict__ H,
                                const float* __restrict__ bias,
                                float* __restrict__ out, int N) {
  int t = blockIdx.x * blockDim.x + threadIdx.x;
  int n = t >> 5, lane = t & 31;
  if (n >= N) return;
  float2 a = unpack2(agg_node(H, n, lane));
  float2 b = __ldg(reinterpret_cast<const float2*>(bias) + lane);
  float y0 = gelu_fast(a.x + b.x);
  float y1 = gelu_fast(a.y + b.y);
  reinterpret_cast<float2*>(out + (size_t)n * D_HID)[lane] = make_float2(y0, y1);
}

// ------- layer-3 agg fused with mean-pool; batch is sorted so a block's 8
// nodes almost always share one graph -> smem-reduce, one flush per block. ---
__global__ void agg_pool_kernel(const float* __restrict__ H,
                                const void* __restrict__ batch, int N) {
  __shared__ float sacc[D_HID];
  __shared__ int   scnt;
  __shared__ int   sg;
  int tid  = threadIdx.x;
  int lane = tid & 31, wid = tid >> 5;
  int n = blockIdx.x * 8 + wid;

  if (tid == 0) {
    scnt = 0;
    int first = blockIdx.x * 8;
    sg = load_idx(batch, first < N ? first : (N - 1));
  }
  if (tid < D_HID) sacc[tid] = 0.0f;
  __syncthreads();

  if (n < N) {
    float2 a = unpack2(agg_node(H, n, lane));
    int g = load_idx(batch, n);
    if (g == sg) {
      atomicAdd(&sacc[lane * 2],     a.x);
      atomicAdd(&sacc[lane * 2 + 1], a.y);
      if (lane == 0) atomicAdd(&scnt, 1);
    } else {
      atomicAdd(&g_psum[g * D_HID + lane * 2],     a.x);
      atomicAdd(&g_psum[g * D_HID + lane * 2 + 1], a.y);
      if (lane == 0) atomicAdd(&g_pcnt[g], 1);
    }
  }
  __syncthreads();
  if (scnt > 0) {
    if (tid < D_HID) atomicAdd(&g_psum[sg * D_HID + tid], sacc[tid]);
    if (tid == 0)    atomicAdd(&g_pcnt[sg], scnt);
  }
}

// ------- final tiny GEMM: out[g,:] = mean_g @ W3 + b3 -----------------------
__global__ void final_gemm_kernel(const float* __restrict__ W3,
                                  const float* __restrict__ b3,
                                  float* __restrict__ out) {
  int g = blockIdx.x;
  int j = threadIdx.x;  // 128 threads = D_OUT
  __shared__ float row[D_HID];
  int cnt = g_pcnt[g];
  float inv = (cnt > 0) ? (1.0f / (float)cnt) : 0.0f;
  if (j < D_HID) row[j] = g_psum[g * D_HID + j] * inv;
  __syncthreads();
  float acc = (cnt > 0) ? __ldg(&b3[j]) : 0.0f;
#pragma unroll 8
  for (int k = 0; k < D_HID; k++) acc += row[k] * __ldg(&W3[k * D_OUT + j]);
  out[(size_t)g * D_OUT + j] = acc;
}

// ---------------- launch ----------------
extern "C" void kernel_launch(void* const* d_in, const int* in_sizes, int n_in,
                              void* d_out, int out_size) {
  const float* x     = (const float*)d_in[0];
  const void*  ei    = d_in[1];
  const void*  batch = d_in[2];

  int wi = 3;
  while (wi < n_in && in_sizes[wi] <= 1) wi++;
  const float* W1 = (const float*)d_in[wi + 0];
  const float* b1 = (const float*)d_in[wi + 1];
  const float* W2 = (const float*)d_in[wi + 2];
  const float* b2 = (const float*)d_in[wi + 3];
  const float* W3 = (const float*)d_in[wi + 4];
  const float* b3 = (const float*)d_in[wi + 5];

  int N = in_sizes[2];
  int E = in_sizes[1] / 2;

  float *bufA, *bufB;
  cudaGetSymbolAddress((void**)&bufA, g_bufA);
  cudaGetSymbolAddress((void**)&bufB, g_bufB);

  const int TB = 256;
  int nb_nodes = (N + TB - 1) / TB;
  int nb_edges = (E + TB - 1) / TB;
  int nb_warp  = (int)(((long long)N * 32 + TB - 1) / TB);
  int nb_gemm  = (N + 127) / 128;

  // ---- preprocessing: CSR + symmetric norm ----
  init_kernel<<<nb_nodes, TB>>>(ei, N, N);
  hist_kernel<<<nb_edges, TB>>>(ei, E);
  scan_kernel<<<1, 1024>>>(N);
  scatter_kernel<<<nb_edges, TB>>>(E);

  // ---- layer 1: GEMM 128->64, agg + gelu ----
  gemm_kernel<D_IN><<<nb_gemm, TB>>>(x, W1, bufA, N);
  agg_gelu_kernel<<<nb_warp, TB>>>(bufA, b1, bufB, N);

  // ---- layer 2: GEMM 64->64, agg + gelu ----
  gemm_kernel<D_HID><<<nb_gemm, TB>>>(bufB, W2, bufA, N);
  agg_gelu_kernel<<<nb_warp, TB>>>(bufA, b2, bufB, N);

  // ---- layer 3 (reordered): agg+pool in 64-dim, then [NG,64]@[64,128]+b3 ----
  agg_pool_kernel<<<(N + 7) / 8, TB>>>(bufB, batch, N);
  final_gemm_kernel<<<out_size / D_OUT, D_OUT>>>(W3, b3, (float*)d_out);
}